// round 2
// baseline (speedup 1.0000x reference)
#include <cuda_runtime.h>

#define F 64
#define NT 4

// Node counts (fixed by the problem)
#define N_HIT 300000
#define N_SP   50000
#define N_OPH 200000
#define N_PMT  30000
#define N_OPF   2000
#define N_EVT    256

// Scratch: interleaved (den,num) accumulators, max target count = N_HIT.
// Layout: g_acc[t*128 + 4*l + {0,1,2,3}] = {den(f=2l), num(f=2l), den(f=2l+1), num(f=2l+1)}
__device__ float g_acc[(size_t)N_HIT * 128];
__device__ float g_nbuf[(size_t)N_SP * F];
__device__ float g_pmtbuf[(size_t)N_PMT * F];
__device__ float g_opfbuf[(size_t)N_OPF * F];

// Packed fp32x2 FMA (Blackwell FFMA2, only via PTX)
__device__ __forceinline__ float2 ffma2(float2 a, float2 b, float2 c) {
    unsigned long long ua = *reinterpret_cast<unsigned long long*>(&a);
    unsigned long long ub = *reinterpret_cast<unsigned long long*>(&b);
    unsigned long long uc = *reinterpret_cast<unsigned long long*>(&c);
    unsigned long long ud;
    asm("fma.rn.f32x2 %0, %1, %2, %3;" : "=l"(ud) : "l"(ua), "l"(ub), "l"(uc));
    return *reinterpret_cast<float2*>(&ud);
}

// mish(x) = x*tanh(softplus(x)) = x * (e(e+2))/(e(e+2)+2), e = exp(x)
__device__ __forceinline__ float mishf(float x) {
    float e = __expf(fminf(x, 30.f));
    float t = e * (e + 2.f);
    return x * __fdividef(t, t + 2.f);
}

// One warp per edge: gather x_i/x_j, sigmoid attention dot, m = w*x_j,
// accumulate (exp(m), exp(m)*m) into target's (den,num) with one float4 RED per lane.
__global__ void edge_pass(const float* __restrict__ xsrc, const float* __restrict__ xtgt,
                          const int* __restrict__ src, const int* __restrict__ dst, int E,
                          const float* __restrict__ eW, const float* __restrict__ eB) {
    __shared__ float Ws[2 * F];
    __shared__ float Bs;
    int tid = threadIdx.x;
    if (tid < 2 * F) Ws[tid] = eW[tid];
    if (tid == 0) Bs = eB[0];
    __syncthreads();

    int lane = tid & 31;
    int e = blockIdx.x * (blockDim.x >> 5) + (tid >> 5);
    if (e >= E) return;

    int s = src[e], d = dst[e];
    float2 xj = *reinterpret_cast<const float2*>(xsrc + (size_t)s * F + 2 * lane);
    float2 xi = *reinterpret_cast<const float2*>(xtgt + (size_t)d * F + 2 * lane);

    // cat = [x_i, x_j] dot edge_w
    float part = xi.x * Ws[2 * lane] + xi.y * Ws[2 * lane + 1]
               + xj.x * Ws[F + 2 * lane] + xj.y * Ws[F + 2 * lane + 1];
#pragma unroll
    for (int o = 16; o; o >>= 1) part += __shfl_xor_sync(0xffffffffu, part, o);

    float w = __fdividef(1.f, 1.f + __expf(-(part + Bs)));
    float m0 = w * xj.x, m1 = w * xj.y;
    float e0 = __expf(m0), e1 = __expf(m1);

    float4 v = make_float4(e0, e0 * m0, e1, e1 * m1);
    atomicAdd(reinterpret_cast<float4*>(g_acc + (size_t)d * 128 + 4 * lane), v);
}

// One warp per NT nodes: aggr = num/(den+eps), h=mish([aggr,x]@W1+b1), out=mish(h@W2+b2).
// Weights in shared; broadcast operand duplicated in shared so FFMA2 consumes it directly.
// Also zeroes the consumed g_acc range (keeps scratch invariant across graph replays).
__global__ void __launch_bounds__(256, 2) node_pass(
    const float* __restrict__ xtgt, int n_tgt,
    const float* __restrict__ w1, const float* __restrict__ b1,
    const float* __restrict__ w2, const float* __restrict__ b2,
    float* __restrict__ out, int accumulate) {
    extern __shared__ float sm[];
    float*  w1s  = sm;            // 8192 floats
    float*  w2s  = sm + 8192;     // 4096 floats
    float*  b1s  = sm + 12288;    // 64
    float*  b2s  = sm + 12352;    // 64
    float2* cats = reinterpret_cast<float2*>(sm + 12416);  // 8 warps * NT * 128 float2

    int tid = threadIdx.x;
    {
        const float4* s1 = reinterpret_cast<const float4*>(w1);
        float4*       d1 = reinterpret_cast<float4*>(w1s);
        for (int i = tid; i < 2048; i += 256) d1[i] = s1[i];
        const float4* s2 = reinterpret_cast<const float4*>(w2);
        float4*       d2 = reinterpret_cast<float4*>(w2s);
        for (int i = tid; i < 1024; i += 256) d2[i] = s2[i];
        if (tid < 64) { b1s[tid] = b1[tid]; b2s[tid] = b2[tid]; }
    }
    __syncthreads();

    int warp = tid >> 5, lane = tid & 31;
    float2* cw = cats + warp * NT * 128;
    int stride = gridDim.x * 8 * NT;

    for (int base = (blockIdx.x * 8 + warp) * NT; base < n_tgt; base += stride) {
        int nv = n_tgt - base; if (nv > NT) nv = NT;

#pragma unroll
        for (int t = 0; t < NT; t++) {
            if (t < nv) {
                size_t node = (size_t)(base + t);
                float4* ap = reinterpret_cast<float4*>(g_acc + node * 128 + 4 * lane);
                float4 a = *ap;
                *ap = make_float4(0.f, 0.f, 0.f, 0.f);  // self-clean for next block / replay
                float2 xt = *reinterpret_cast<const float2*>(xtgt + node * F + 2 * lane);
                float a0 = __fdividef(a.y, a.x + 1e-16f);
                float a1 = __fdividef(a.w, a.z + 1e-16f);
                cw[t * 128 + 2 * lane]          = make_float2(a0, a0);
                cw[t * 128 + 2 * lane + 1]      = make_float2(a1, a1);
                cw[t * 128 + 64 + 2 * lane]     = make_float2(xt.x, xt.x);
                cw[t * 128 + 64 + 2 * lane + 1] = make_float2(xt.y, xt.y);
            }
        }
        __syncwarp();

        float2 acc[NT];
        float2 bv1 = *reinterpret_cast<float2*>(b1s + 2 * lane);
#pragma unroll
        for (int t = 0; t < NT; t++) acc[t] = bv1;
#pragma unroll 4
        for (int k = 0; k < 128; k++) {
            float2 wv = *reinterpret_cast<float2*>(w1s + k * 64 + 2 * lane);
#pragma unroll
            for (int t = 0; t < NT; t++) acc[t] = ffma2(wv, cw[t * 128 + k], acc[t]);
        }
        __syncwarp();

#pragma unroll
        for (int t = 0; t < NT; t++) {
            float h0 = mishf(acc[t].x), h1 = mishf(acc[t].y);
            cw[t * 128 + 2 * lane]     = make_float2(h0, h0);
            cw[t * 128 + 2 * lane + 1] = make_float2(h1, h1);
        }
        __syncwarp();

        float2 bv2 = *reinterpret_cast<float2*>(b2s + 2 * lane);
#pragma unroll
        for (int t = 0; t < NT; t++) acc[t] = bv2;
#pragma unroll 4
        for (int k = 0; k < 64; k++) {
            float2 wv = *reinterpret_cast<float2*>(w2s + k * 64 + 2 * lane);
#pragma unroll
            for (int t = 0; t < NT; t++) acc[t] = ffma2(wv, cw[t * 128 + k], acc[t]);
        }

#pragma unroll
        for (int t = 0; t < NT; t++) {
            if (t < nv) {
                float o0 = mishf(acc[t].x), o1 = mishf(acc[t].y);
                float2* op = reinterpret_cast<float2*>(out + (size_t)(base + t) * F + 2 * lane);
                if (accumulate) { float2 pv = *op; o0 += pv.x; o1 += pv.y; }
                *op = make_float2(o0, o1);
            }
        }
        __syncwarp();
    }
}

extern "C" void kernel_launch(void* const* d_in, const int* in_sizes, int n_in,
                              void* d_out, int out_size) {
    const float* x_hit = (const float*)d_in[0];
    const float* x_sp  = (const float*)d_in[1];
    const float* x_oph = (const float*)d_in[2];
    const float* x_pmt = (const float*)d_in[3];
    const float* x_opf = (const float*)d_in[4];
    const float* x_evt = (const float*)d_in[5];
    const float* ew = (const float*)d_in[6];
    const float* eb = (const float*)d_in[7];
    const float* w1 = (const float*)d_in[8];
    const float* b1 = (const float*)d_in[9];
    const float* w2 = (const float*)d_in[10];
    const float* b2 = (const float*)d_in[11];
    const int* e_hit_sp  = (const int*)d_in[12];
    const int* e_oph_pmt = (const int*)d_in[13];
    const int* e_pmt_opf = (const int*)d_in[14];
    const int* e_sp_evt  = (const int*)d_in[15];
    const int* e_opf_evt = (const int*)d_in[16];
    const int* e_evt_sp  = (const int*)d_in[17];
    const int* e_sp_hit  = (const int*)d_in[18];
    const int* e_evt_opf = (const int*)d_in[19];
    const int* e_opf_pmt = (const int*)d_in[20];
    const int* e_pmt_oph = (const int*)d_in[21];

    float* out = (float*)d_out;
    float* d_p   = out;
    float* d_n   = d_p   + (size_t)N_HIT * F;
    float* d_oph = d_n   + (size_t)N_SP  * F;
    float* d_pmt = d_oph + (size_t)N_OPH * F;
    float* d_opf = d_pmt + (size_t)N_PMT * F;
    float* d_i   = d_opf + (size_t)N_OPF * F;

    float *pn = nullptr, *ppmt = nullptr, *popf = nullptr;
    cudaGetSymbolAddress((void**)&pn,   g_nbuf);
    cudaGetSymbolAddress((void**)&ppmt, g_pmtbuf);
    cudaGetSymbolAddress((void**)&popf, g_opfbuf);

    const int SMEM = 82432;
    // Attribute persists from the first (non-captured) correctness call; ignore errors in-capture.
    cudaFuncSetAttribute(node_pass, cudaFuncAttributeMaxDynamicSharedMemorySize, SMEM);

    auto blk = [&](int i, const float* xs, const float* xt, const int* e, int E,
                   int n_tgt, float* o, int accf) {
        int grid = (E + 15) / 16;  // 512 threads = 16 warps = 16 edges/block
        edge_pass<<<grid, 512>>>(xs, xt, e, e + E, E, ew + (size_t)i * 128, eb + i);
        node_pass<<<296, 256, SMEM>>>(xt, n_tgt, w1 + (size_t)i * 8192, b1 + (size_t)i * 64,
                                      w2 + (size_t)i * 4096, b2 + (size_t)i * 64, o, accf);
    };

    int E_hs  = in_sizes[12] / 2;
    int E_op  = in_sizes[13] / 2;
    int E_po  = in_sizes[14] / 2;
    int E_se  = in_sizes[15] / 2;
    int E_oe  = in_sizes[16] / 2;
    int E_es  = in_sizes[17] / 2;
    int E_sh  = in_sizes[18] / 2;
    int E_eo  = in_sizes[19] / 2;
    int E_opm = in_sizes[20] / 2;
    int E_pmo = in_sizes[21] / 2;

    blk(0, x_hit, x_sp,  e_hit_sp,  E_hs,  N_SP,  pn,    0);  // plane_to_nexus
    blk(1, x_oph, x_pmt, e_oph_pmt, E_op,  N_PMT, ppmt,  0);  // hit_to_pmt
    blk(2, ppmt,  x_opf, e_pmt_opf, E_po,  N_OPF, popf,  0);  // pmt_to_flash
    blk(3, pn,    x_evt, e_sp_evt,  E_se,  N_EVT, d_i,   0);  // nexus_to_interaction
    blk(4, popf,  x_evt, e_opf_evt, E_oe,  N_EVT, d_i,   1);  // flash_to_interaction (sum)
    blk(5, d_i,   pn,    e_evt_sp,  E_es,  N_SP,  d_n,   0);  // interaction_to_nexus
    blk(6, d_n,   x_hit, e_sp_hit,  E_sh,  N_HIT, d_p,   0);  // nexus_to_plane
    blk(7, d_i,   popf,  e_evt_opf, E_eo,  N_OPF, d_opf, 0);  // interaction_to_flash
    blk(8, d_opf, ppmt,  e_opf_pmt, E_opm, N_PMT, d_pmt, 0);  // flash_to_pmt
    blk(9, d_pmt, x_oph, e_pmt_oph, E_pmo, N_OPH, d_oph, 0);  // pmt_to_ophit
}

// round 4
// speedup vs baseline: 1.4518x; 1.4518x over previous
#include <cuda_runtime.h>

#define F 64
#define NT 4

// Node counts (fixed by the problem)
#define N_HIT 300000
#define N_SP   50000
#define N_OPH 200000
#define N_PMT  30000
#define N_OPF   2000
#define N_EVT    256
#define MAX_E  400000

// ---- scratch (device globals; zero-initialized at load) ----
// Small-pass atomic accumulators only (evt/opf targets): 2000 * 128 floats = 1MB
__device__ float g_acc[(size_t)N_OPF * 128];
// Intermediate node features
__device__ float g_nbuf[(size_t)N_SP * F];
__device__ float g_pmtbuf[(size_t)N_PMT * F];
__device__ float g_opfbuf[(size_t)N_OPF * F];
// Sort machinery
__device__ int   g_count[N_HIT];
__device__ int   g_offs[N_HIT];
__device__ int   g_cursor[N_HIT];
__device__ int   g_ssrc[MAX_E];
__device__ int   g_bsums[128];
__device__ float g_dotj[N_HIT];

// Packed fp32x2 FMA (Blackwell FFMA2, only via PTX)
__device__ __forceinline__ float2 ffma2(float2 a, float2 b, float2 c) {
    unsigned long long ua = *reinterpret_cast<unsigned long long*>(&a);
    unsigned long long ub = *reinterpret_cast<unsigned long long*>(&b);
    unsigned long long uc = *reinterpret_cast<unsigned long long*>(&c);
    unsigned long long ud;
    asm("fma.rn.f32x2 %0, %1, %2, %3;" : "=l"(ud) : "l"(ua), "l"(ub), "l"(uc));
    return *reinterpret_cast<float2*>(&ud);
}

__device__ __forceinline__ float mishf(float x) {
    float e = __expf(fminf(x, 30.f));
    float t = e * (e + 2.f);
    return x * __fdividef(t, t + 2.f);
}

// ======================= sort machinery kernels =======================

__global__ void zero_k(int* __restrict__ p, int n) {
    int i = blockIdx.x * blockDim.x + threadIdx.x;
    for (; i < n; i += gridDim.x * blockDim.x) p[i] = 0;
}

__global__ void hist_k(const int* __restrict__ dst, int E, int* __restrict__ cnt) {
    int i = blockIdx.x * blockDim.x + threadIdx.x;
    if (i < E) atomicAdd(&cnt[dst[i]], 1);
}

#define SCHUNK 4096
__global__ void scan1_k(const int* __restrict__ cnt, int n, int* __restrict__ bsums) {
    __shared__ int ts[256];
    int tid = threadIdx.x;
    int base = blockIdx.x * SCHUNK;
    int s = 0;
#pragma unroll
    for (int j = 0; j < 16; j++) {
        int i = base + j * 256 + tid;
        if (i < n) s += cnt[i];
    }
    ts[tid] = s; __syncthreads();
    for (int o = 128; o; o >>= 1) { if (tid < o) ts[tid] += ts[tid + o]; __syncthreads(); }
    if (!tid) bsums[blockIdx.x] = ts[0];
}

__global__ void scan2_k(int* __restrict__ bsums, int nb) {
    __shared__ int sb[128];
    int tid = threadIdx.x;
    if (tid < nb) sb[tid] = bsums[tid];
    __syncthreads();
    if (tid == 0) {
        int run = 0;
        for (int b = 0; b < nb; b++) { int t = sb[b]; sb[b] = run; run += t; }
    }
    __syncthreads();
    if (tid < nb) bsums[tid] = sb[tid];
}

__global__ void scan3_k(const int* __restrict__ cnt, const int* __restrict__ bsums, int n,
                        int* __restrict__ offs, int* __restrict__ cur) {
    __shared__ int ts[256];
    int tid = threadIdx.x;
    int base = blockIdx.x * SCHUNK + tid * 16;
    int v[16]; int s = 0;
#pragma unroll
    for (int j = 0; j < 16; j++) {
        int i = base + j;
        v[j] = (i < n) ? cnt[i] : 0;
        s += v[j];
    }
    ts[tid] = s; __syncthreads();
    for (int off = 1; off < 256; off <<= 1) {
        int add = (tid >= off) ? ts[tid - off] : 0;
        __syncthreads();
        ts[tid] += add;
        __syncthreads();
    }
    int run = (tid ? ts[tid - 1] : 0) + bsums[blockIdx.x];
#pragma unroll
    for (int j = 0; j < 16; j++) {
        int i = base + j;
        if (i < n) { offs[i] = run; cur[i] = run; run += v[j]; }
    }
}

__global__ void scatter_k(const int* __restrict__ src, const int* __restrict__ dst, int E,
                          int* __restrict__ cur, int* __restrict__ ssrc) {
    int i = blockIdx.x * blockDim.x + threadIdx.x;
    if (i < E) {
        int pos = atomicAdd(&cur[dst[i]], 1);
        ssrc[pos] = src[i];
    }
}

// dotJ[n] = x_src[n] . edge_w[64:128]   (one warp per node)
__global__ void dotj_k(const float* __restrict__ xsrc, int n_src,
                       const float* __restrict__ eW, float* __restrict__ dotj) {
    int lane = threadIdx.x & 31;
    int node = (blockIdx.x * blockDim.x + threadIdx.x) >> 5;
    float wj0 = eW[64 + 2 * lane], wj1 = eW[65 + 2 * lane];
    if (node >= n_src) return;
    float2 x = *reinterpret_cast<const float2*>(xsrc + (size_t)node * F + 2 * lane);
    float p = x.x * wj0 + x.y * wj1;
#pragma unroll
    for (int o = 16; o; o >>= 1) p += __shfl_xor_sync(0xffffffffu, p, o);
    if (!lane) dotj[node] = p;
}

// ======================= fused segment-reduce + MLP =======================
// One warp owns NT=4 targets. Per target: load x_i, reduce dotI, iterate its
// sorted edges (4 interleaved chains across targets), softmax-aggregate in
// registers, then run the 2-layer Mish MLP with FFMA2 on shared weights.
__global__ void __launch_bounds__(256, 2) fused_pass(
    const float* __restrict__ xsrc, const float* __restrict__ xtgt, int n_tgt,
    const int* __restrict__ ssrc, const int* __restrict__ offs, const int* __restrict__ cnt,
    const float* __restrict__ dotj,
    const float* __restrict__ eW, const float* __restrict__ eB,
    const float* __restrict__ w1, const float* __restrict__ b1,
    const float* __restrict__ w2, const float* __restrict__ b2,
    float* __restrict__ out) {
    extern __shared__ float sm[];
    float*  w1s  = sm;            // 8192 floats
    float*  w2s  = sm + 8192;     // 4096 floats
    float*  b1s  = sm + 12288;    // 64
    float*  b2s  = sm + 12352;    // 64
    float2* cats = reinterpret_cast<float2*>(sm + 12416);  // 8 warps * NT * 128 float2

    int tid = threadIdx.x;
    {
        const float4* s1 = reinterpret_cast<const float4*>(w1);
        float4*       d1 = reinterpret_cast<float4*>(w1s);
        for (int i = tid; i < 2048; i += 256) d1[i] = s1[i];
        const float4* s2 = reinterpret_cast<const float4*>(w2);
        float4*       d2 = reinterpret_cast<float4*>(w2s);
        for (int i = tid; i < 1024; i += 256) d2[i] = s2[i];
        if (tid < 64) { b1s[tid] = b1[tid]; b2s[tid] = b2[tid]; }
    }
    __syncthreads();

    int warp = tid >> 5, lane = tid & 31;
    float wi0 = eW[2 * lane], wi1 = eW[2 * lane + 1];
    float bia = eB[0];
    float2* cw = cats + warp * NT * 128;
    int stride = gridDim.x * 8 * NT;

    for (int base = (blockIdx.x * 8 + warp) * NT; base < n_tgt; base += stride) {
        int nv = n_tgt - base; if (nv > NT) nv = NT;

        int o[NT], c[NT];
        float2 xiv[NT];
        float dot_i[NT];
#pragma unroll
        for (int t = 0; t < NT; t++) {
            bool v = (t < nv);
            size_t node = (size_t)(base + t);
            o[t] = v ? offs[node] : 0;
            c[t] = v ? cnt[node]  : 0;
            xiv[t] = v ? *reinterpret_cast<const float2*>(xtgt + node * F + 2 * lane)
                       : make_float2(0.f, 0.f);
            float p = xiv[t].x * wi0 + xiv[t].y * wi1;
#pragma unroll
            for (int off = 16; off; off >>= 1) p += __shfl_xor_sync(0xffffffffu, p, off);
            dot_i[t] = p + bia;
        }

        int maxc = c[0];
#pragma unroll
        for (int t = 1; t < NT; t++) maxc = max(maxc, c[t]);

        float den0[NT], num0[NT], den1[NT], num1[NT];
#pragma unroll
        for (int t = 0; t < NT; t++) { den0[t] = 0.f; num0[t] = 0.f; den1[t] = 0.f; num1[t] = 0.f; }

        for (int k = 0; k < maxc; k++) {
            float  djv[NT];
            float2 xjv[NT];
#pragma unroll
            for (int t = 0; t < NT; t++) {
                if (k < c[t]) {
                    int s = ssrc[o[t] + k];
                    djv[t] = dotj[s];
                    xjv[t] = *reinterpret_cast<const float2*>(xsrc + (size_t)s * F + 2 * lane);
                }
            }
#pragma unroll
            for (int t = 0; t < NT; t++) {
                if (k < c[t]) {
                    float z = dot_i[t] + djv[t];
                    float w = __fdividef(1.f, 1.f + __expf(-z));
                    float m0 = w * xjv[t].x, m1 = w * xjv[t].y;
                    float e0 = __expf(m0),   e1 = __expf(m1);
                    den0[t] += e0; num0[t] += e0 * m0;
                    den1[t] += e1; num1[t] += e1 * m1;
                }
            }
        }

#pragma unroll
        for (int t = 0; t < NT; t++) {
            float a0 = __fdividef(num0[t], den0[t] + 1e-16f);
            float a1 = __fdividef(num1[t], den1[t] + 1e-16f);
            cw[t * 128 + 2 * lane]          = make_float2(a0, a0);
            cw[t * 128 + 2 * lane + 1]      = make_float2(a1, a1);
            cw[t * 128 + 64 + 2 * lane]     = make_float2(xiv[t].x, xiv[t].x);
            cw[t * 128 + 64 + 2 * lane + 1] = make_float2(xiv[t].y, xiv[t].y);
        }
        __syncwarp();

        float2 acc[NT];
        float2 bv1 = *reinterpret_cast<float2*>(b1s + 2 * lane);
#pragma unroll
        for (int t = 0; t < NT; t++) acc[t] = bv1;
#pragma unroll 4
        for (int k = 0; k < 128; k++) {
            float2 wv = *reinterpret_cast<float2*>(w1s + k * 64 + 2 * lane);
#pragma unroll
            for (int t = 0; t < NT; t++) acc[t] = ffma2(wv, cw[t * 128 + k], acc[t]);
        }
        __syncwarp();

#pragma unroll
        for (int t = 0; t < NT; t++) {
            float h0 = mishf(acc[t].x), h1 = mishf(acc[t].y);
            cw[t * 128 + 2 * lane]     = make_float2(h0, h0);
            cw[t * 128 + 2 * lane + 1] = make_float2(h1, h1);
        }
        __syncwarp();

        float2 bv2 = *reinterpret_cast<float2*>(b2s + 2 * lane);
#pragma unroll
        for (int t = 0; t < NT; t++) acc[t] = bv2;
#pragma unroll 4
        for (int k = 0; k < 64; k++) {
            float2 wv = *reinterpret_cast<float2*>(w2s + k * 64 + 2 * lane);
#pragma unroll
            for (int t = 0; t < NT; t++) acc[t] = ffma2(wv, cw[t * 128 + k], acc[t]);
        }

#pragma unroll
        for (int t = 0; t < NT; t++) {
            if (t < nv) {
                float o0 = mishf(acc[t].x), o1 = mishf(acc[t].y);
                *reinterpret_cast<float2*>(out + (size_t)(base + t) * F + 2 * lane)
                    = make_float2(o0, o1);
            }
        }
        __syncwarp();
    }
}

// ======================= small-pass atomic path (validated round 1) =======================

__global__ void edge_pass(const float* __restrict__ xsrc, const float* __restrict__ xtgt,
                          const int* __restrict__ src, const int* __restrict__ dst, int E,
                          const float* __restrict__ eW, const float* __restrict__ eB) {
    __shared__ float Ws[2 * F];
    __shared__ float Bs;
    int tid = threadIdx.x;
    if (tid < 2 * F) Ws[tid] = eW[tid];
    if (tid == 0) Bs = eB[0];
    __syncthreads();

    int lane = tid & 31;
    int e = blockIdx.x * (blockDim.x >> 5) + (tid >> 5);
    if (e >= E) return;

    int s = src[e], d = dst[e];
    float2 xj = *reinterpret_cast<const float2*>(xsrc + (size_t)s * F + 2 * lane);
    float2 xi = *reinterpret_cast<const float2*>(xtgt + (size_t)d * F + 2 * lane);

    float part = xi.x * Ws[2 * lane] + xi.y * Ws[2 * lane + 1]
               + xj.x * Ws[F + 2 * lane] + xj.y * Ws[F + 2 * lane + 1];
#pragma unroll
    for (int o = 16; o; o >>= 1) part += __shfl_xor_sync(0xffffffffu, part, o);

    float w = __fdividef(1.f, 1.f + __expf(-(part + Bs)));
    float m0 = w * xj.x, m1 = w * xj.y;
    float e0 = __expf(m0), e1 = __expf(m1);

    float4 v = make_float4(e0, e0 * m0, e1, e1 * m1);
    atomicAdd(reinterpret_cast<float4*>(g_acc + (size_t)d * 128 + 4 * lane), v);
}

__global__ void __launch_bounds__(256, 2) node_pass(
    const float* __restrict__ xtgt, int n_tgt,
    const float* __restrict__ w1, const float* __restrict__ b1,
    const float* __restrict__ w2, const float* __restrict__ b2,
    float* __restrict__ out, int accumulate) {
    extern __shared__ float sm[];
    float*  w1s  = sm;
    float*  w2s  = sm + 8192;
    float*  b1s  = sm + 12288;
    float*  b2s  = sm + 12352;
    float2* cats = reinterpret_cast<float2*>(sm + 12416);

    int tid = threadIdx.x;
    {
        const float4* s1 = reinterpret_cast<const float4*>(w1);
        float4*       d1 = reinterpret_cast<float4*>(w1s);
        for (int i = tid; i < 2048; i += 256) d1[i] = s1[i];
        const float4* s2 = reinterpret_cast<const float4*>(w2);
        float4*       d2 = reinterpret_cast<float4*>(w2s);
        for (int i = tid; i < 1024; i += 256) d2[i] = s2[i];
        if (tid < 64) { b1s[tid] = b1[tid]; b2s[tid] = b2[tid]; }
    }
    __syncthreads();

    int warp = tid >> 5, lane = tid & 31;
    float2* cw = cats + warp * NT * 128;
    int stride = gridDim.x * 8 * NT;

    for (int base = (blockIdx.x * 8 + warp) * NT; base < n_tgt; base += stride) {
        int nv = n_tgt - base; if (nv > NT) nv = NT;

#pragma unroll
        for (int t = 0; t < NT; t++) {
            if (t < nv) {
                size_t node = (size_t)(base + t);
                float4* ap = reinterpret_cast<float4*>(g_acc + node * 128 + 4 * lane);
                float4 a = *ap;
                *ap = make_float4(0.f, 0.f, 0.f, 0.f);  // self-clean for replay
                float2 xt = *reinterpret_cast<const float2*>(xtgt + node * F + 2 * lane);
                float a0 = __fdividef(a.y, a.x + 1e-16f);
                float a1 = __fdividef(a.w, a.z + 1e-16f);
                cw[t * 128 + 2 * lane]          = make_float2(a0, a0);
                cw[t * 128 + 2 * lane + 1]      = make_float2(a1, a1);
                cw[t * 128 + 64 + 2 * lane]     = make_float2(xt.x, xt.x);
                cw[t * 128 + 64 + 2 * lane + 1] = make_float2(xt.y, xt.y);
            }
        }
        __syncwarp();

        float2 acc[NT];
        float2 bv1 = *reinterpret_cast<float2*>(b1s + 2 * lane);
#pragma unroll
        for (int t = 0; t < NT; t++) acc[t] = bv1;
#pragma unroll 4
        for (int k = 0; k < 128; k++) {
            float2 wv = *reinterpret_cast<float2*>(w1s + k * 64 + 2 * lane);
#pragma unroll
            for (int t = 0; t < NT; t++) acc[t] = ffma2(wv, cw[t * 128 + k], acc[t]);
        }
        __syncwarp();

#pragma unroll
        for (int t = 0; t < NT; t++) {
            float h0 = mishf(acc[t].x), h1 = mishf(acc[t].y);
            cw[t * 128 + 2 * lane]     = make_float2(h0, h0);
            cw[t * 128 + 2 * lane + 1] = make_float2(h1, h1);
        }
        __syncwarp();

        float2 bv2 = *reinterpret_cast<float2*>(b2s + 2 * lane);
#pragma unroll
        for (int t = 0; t < NT; t++) acc[t] = bv2;
#pragma unroll 4
        for (int k = 0; k < 64; k++) {
            float2 wv = *reinterpret_cast<float2*>(w2s + k * 64 + 2 * lane);
#pragma unroll
            for (int t = 0; t < NT; t++) acc[t] = ffma2(wv, cw[t * 128 + k], acc[t]);
        }

#pragma unroll
        for (int t = 0; t < NT; t++) {
            if (t < nv) {
                float o0 = mishf(acc[t].x), o1 = mishf(acc[t].y);
                float2* op = reinterpret_cast<float2*>(out + (size_t)(base + t) * F + 2 * lane);
                if (accumulate) { float2 pv = *op; o0 += pv.x; o1 += pv.y; }
                *op = make_float2(o0, o1);
            }
        }
        __syncwarp();
    }
}

// ======================= launcher =======================

extern "C" void kernel_launch(void* const* d_in, const int* in_sizes, int n_in,
                              void* d_out, int out_size) {
    const float* x_hit = (const float*)d_in[0];
    const float* x_sp  = (const float*)d_in[1];
    const float* x_oph = (const float*)d_in[2];
    const float* x_pmt = (const float*)d_in[3];
    const float* x_opf = (const float*)d_in[4];
    const float* x_evt = (const float*)d_in[5];
    const float* ew = (const float*)d_in[6];
    const float* eb = (const float*)d_in[7];
    const float* w1 = (const float*)d_in[8];
    const float* b1 = (const float*)d_in[9];
    const float* w2 = (const float*)d_in[10];
    const float* b2 = (const float*)d_in[11];
    const int* e_hit_sp  = (const int*)d_in[12];
    const int* e_oph_pmt = (const int*)d_in[13];
    const int* e_pmt_opf = (const int*)d_in[14];
    const int* e_sp_evt  = (const int*)d_in[15];
    const int* e_opf_evt = (const int*)d_in[16];
    const int* e_evt_sp  = (const int*)d_in[17];
    const int* e_sp_hit  = (const int*)d_in[18];
    const int* e_evt_opf = (const int*)d_in[19];
    const int* e_opf_pmt = (const int*)d_in[20];
    const int* e_pmt_oph = (const int*)d_in[21];

    float* out = (float*)d_out;
    float* d_p   = out;
    float* d_n   = d_p   + (size_t)N_HIT * F;
    float* d_oph = d_n   + (size_t)N_SP  * F;
    float* d_pmt = d_oph + (size_t)N_OPH * F;
    float* d_opf = d_pmt + (size_t)N_PMT * F;
    float* d_i   = d_opf + (size_t)N_OPF * F;

    float *pn, *ppmt, *popf, *pdotj;
    int *pcnt, *poffs, *pcur, *pssrc, *pbs;
    cudaGetSymbolAddress((void**)&pn,    g_nbuf);
    cudaGetSymbolAddress((void**)&ppmt,  g_pmtbuf);
    cudaGetSymbolAddress((void**)&popf,  g_opfbuf);
    cudaGetSymbolAddress((void**)&pdotj, g_dotj);
    cudaGetSymbolAddress((void**)&pcnt,  g_count);
    cudaGetSymbolAddress((void**)&poffs, g_offs);
    cudaGetSymbolAddress((void**)&pcur,  g_cursor);
    cudaGetSymbolAddress((void**)&pssrc, g_ssrc);
    cudaGetSymbolAddress((void**)&pbs,   g_bsums);

    const int SMEM = 82432;
    cudaFuncSetAttribute(node_pass,  cudaFuncAttributeMaxDynamicSharedMemorySize, SMEM);
    cudaFuncSetAttribute(fused_pass, cudaFuncAttributeMaxDynamicSharedMemorySize, SMEM);

    // Large-target pass: sort by dst, precompute dotJ, fused reduce+MLP
    auto large = [&](int i, const float* xs, int n_src, const float* xt, int n_tgt,
                     const int* e, int E, float* o) {
        const int* src = e;
        const int* dst = e + E;
        int nb = (n_tgt + SCHUNK - 1) / SCHUNK;
        zero_k   <<<(n_tgt + 255) / 256 < 296 ? (n_tgt + 255) / 256 : 296, 256>>>(pcnt, n_tgt);
        hist_k   <<<(E + 255) / 256, 256>>>(dst, E, pcnt);
        scan1_k  <<<nb, 256>>>(pcnt, n_tgt, pbs);
        scan2_k  <<<1, 128>>>(pbs, nb);
        scan3_k  <<<nb, 256>>>(pcnt, pbs, n_tgt, poffs, pcur);
        scatter_k<<<(E + 255) / 256, 256>>>(src, dst, E, pcur, pssrc);
        dotj_k   <<<(n_src + 7) / 8, 256>>>(xs, n_src, ew + (size_t)i * 128, pdotj);
        int fg = (n_tgt + 8 * NT - 1) / (8 * NT); if (fg > 296) fg = 296;
        fused_pass<<<fg, 256, SMEM>>>(xs, xt, n_tgt, pssrc, poffs, pcnt, pdotj,
                                      ew + (size_t)i * 128, eb + i,
                                      w1 + (size_t)i * 8192, b1 + (size_t)i * 64,
                                      w2 + (size_t)i * 4096, b2 + (size_t)i * 64, o);
    };

    // Small-target pass: atomic RED into g_acc (L2-resident) + node MLP
    auto small = [&](int i, const float* xs, const float* xt, const int* e, int E,
                     int n_tgt, float* o, int accf) {
        int grid = (E + 15) / 16;
        edge_pass<<<grid, 512>>>(xs, xt, e, e + E, E, ew + (size_t)i * 128, eb + i);
        int ng = (n_tgt + 8 * NT - 1) / (8 * NT); if (ng > 296) ng = 296;
        node_pass<<<ng, 256, SMEM>>>(xt, n_tgt, w1 + (size_t)i * 8192, b1 + (size_t)i * 64,
                                     w2 + (size_t)i * 4096, b2 + (size_t)i * 64, o, accf);
    };

    int E_hs  = in_sizes[12] / 2;
    int E_op  = in_sizes[13] / 2;
    int E_po  = in_sizes[14] / 2;
    int E_se  = in_sizes[15] / 2;
    int E_oe  = in_sizes[16] / 2;
    int E_es  = in_sizes[17] / 2;
    int E_sh  = in_sizes[18] / 2;
    int E_eo  = in_sizes[19] / 2;
    int E_opm = in_sizes[20] / 2;
    int E_pmo = in_sizes[21] / 2;

    large(0, x_hit, N_HIT, x_sp,  N_SP,  e_hit_sp,  E_hs,  pn);     // plane_to_nexus
    large(1, x_oph, N_OPH, x_pmt, N_PMT, e_oph_pmt, E_op,  ppmt);   // hit_to_pmt
    small(2, ppmt,  x_opf, e_pmt_opf, E_po,  N_OPF, popf, 0);       // pmt_to_flash
    small(3, pn,    x_evt, e_sp_evt,  E_se,  N_EVT, d_i,  0);       // nexus_to_interaction
    small(4, popf,  x_evt, e_opf_evt, E_oe,  N_EVT, d_i,  1);       // flash_to_interaction (sum)
    large(5, d_i,   N_EVT, pn,    N_SP,  e_evt_sp,  E_es,  d_n);    // interaction_to_nexus
    large(6, d_n,   N_SP,  x_hit, N_HIT, e_sp_hit,  E_sh,  d_p);    // nexus_to_plane
    small(7, d_i,   popf,  e_evt_opf, E_eo,  N_OPF, d_opf, 0);      // interaction_to_flash
    large(8, d_opf, N_OPF, ppmt,  N_PMT, e_opf_pmt, E_opm, d_pmt);  // flash_to_pmt
    large(9, d_pmt, N_PMT, x_oph, N_OPH, e_pmt_oph, E_pmo, d_oph);  // pmt_to_ophit
}

// round 5
// speedup vs baseline: 1.5363x; 1.0582x over previous
#include <cuda_runtime.h>

#define F 64
#define NT 4

// Node counts (fixed by the problem)
#define N_HIT 300000
#define N_SP   50000
#define N_OPH 200000
#define N_PMT  30000
#define N_OPF   2000
#define N_EVT    256

// Combined-sort totals (6 large passes: p0,p1,p5,p6,p8,p9)
#define CTOT 660000     // 50k+30k+50k+300k+30k+200k target slots
#define ETOT 1510000    // 300k+400k+50k+300k+60k+400k edges
#define DTOT 600000     // dotj slots (582,256 used)

// ---- scratch (device globals) ----
__device__ float g_acc[(size_t)N_OPF * 128];   // small-pass atomic accumulators (1MB)
__device__ float g_nbuf[(size_t)N_SP * F];
__device__ float g_pmtbuf[(size_t)N_PMT * F];
__device__ float g_opfbuf[(size_t)N_OPF * F];
__device__ int   g_count[CTOT];
__device__ int   g_offs[CTOT];
__device__ int   g_cursor[CTOT];
__device__ int   g_ssrc[ETOT];
__device__ int   g_bsums[128];
__device__ float g_dotj[DTOT];

// Packed fp32x2 FMA (Blackwell FFMA2, only via PTX)
__device__ __forceinline__ float2 ffma2(float2 a, float2 b, float2 c) {
    unsigned long long ua = *reinterpret_cast<unsigned long long*>(&a);
    unsigned long long ub = *reinterpret_cast<unsigned long long*>(&b);
    unsigned long long uc = *reinterpret_cast<unsigned long long*>(&c);
    unsigned long long ud;
    asm("fma.rn.f32x2 %0, %1, %2, %3;" : "=l"(ud) : "l"(ua), "l"(ub), "l"(uc));
    return *reinterpret_cast<float2*>(&ud);
}

__device__ __forceinline__ float mishf(float x) {
    float e = __expf(fminf(x, 30.f));
    float t = e * (e + 2.f);
    return x * __fdividef(t, t + 2.f);
}

// ======================= batched sort machinery =======================

struct SortCfg {
    const int* src[6];
    const int* dst[6];
    int ebase[7];   // prefix over edge counts
    int cbase[6];   // prefix over target counts
};

__global__ void zero_k(int* __restrict__ p, int n) {
    int i = blockIdx.x * blockDim.x + threadIdx.x;
    for (; i < n; i += gridDim.x * blockDim.x) p[i] = 0;
}

__global__ void hist_all(SortCfg cfg, int Etot, int* __restrict__ cnt) {
    int i = blockIdx.x * blockDim.x + threadIdx.x;
    if (i >= Etot) return;
    int s = 0;
    while (i >= cfg.ebase[s + 1]) s++;
    int li = i - cfg.ebase[s];
    atomicAdd(&cnt[cfg.cbase[s] + cfg.dst[s][li]], 1);
}

#define SCHUNK 8192
__global__ void scan1_k(const int* __restrict__ cnt, int n, int* __restrict__ bsums) {
    __shared__ int ts[256];
    int tid = threadIdx.x;
    int base = blockIdx.x * SCHUNK;
    int s = 0;
#pragma unroll
    for (int j = 0; j < 32; j++) {
        int i = base + j * 256 + tid;
        if (i < n) s += cnt[i];
    }
    ts[tid] = s; __syncthreads();
    for (int o = 128; o; o >>= 1) { if (tid < o) ts[tid] += ts[tid + o]; __syncthreads(); }
    if (!tid) bsums[blockIdx.x] = ts[0];
}

__global__ void scan2_k(int* __restrict__ bsums, int nb) {
    __shared__ int sb[128];
    int tid = threadIdx.x;
    if (tid < nb) sb[tid] = bsums[tid];
    __syncthreads();
    if (tid == 0) {
        int run = 0;
        for (int b = 0; b < nb; b++) { int t = sb[b]; sb[b] = run; run += t; }
    }
    __syncthreads();
    if (tid < nb) bsums[tid] = sb[tid];
}

__global__ void scan3_k(const int* __restrict__ cnt, const int* __restrict__ bsums, int n,
                        int* __restrict__ offs, int* __restrict__ cur) {
    __shared__ int ts[256];
    int tid = threadIdx.x;
    int base = blockIdx.x * SCHUNK + tid * 32;
    int v[32]; int s = 0;
#pragma unroll
    for (int j = 0; j < 32; j++) {
        int i = base + j;
        v[j] = (i < n) ? cnt[i] : 0;
        s += v[j];
    }
    ts[tid] = s; __syncthreads();
    for (int off = 1; off < 256; off <<= 1) {
        int add = (tid >= off) ? ts[tid - off] : 0;
        __syncthreads();
        ts[tid] += add;
        __syncthreads();
    }
    int run = (tid ? ts[tid - 1] : 0) + bsums[blockIdx.x];
#pragma unroll
    for (int j = 0; j < 32; j++) {
        int i = base + j;
        if (i < n) { offs[i] = run; cur[i] = run; run += v[j]; }
    }
}

__global__ void scatter_all(SortCfg cfg, int Etot, int* __restrict__ cur, int* __restrict__ ssrc) {
    int i = blockIdx.x * blockDim.x + threadIdx.x;
    if (i >= Etot) return;
    int s = 0;
    while (i >= cfg.ebase[s + 1]) s++;
    int li = i - cfg.ebase[s];
    int pos = atomicAdd(&cur[cfg.cbase[s] + cfg.dst[s][li]], 1);
    ssrc[pos] = cfg.src[s][li];
}

// dotJ[n] = x_src[n] . edge_w[64:128]   (one warp per node)
__global__ void dotj_k(const float* __restrict__ xsrc, int n_src,
                       const float* __restrict__ eW, float* __restrict__ dotj) {
    int lane = threadIdx.x & 31;
    int node = (blockIdx.x * blockDim.x + threadIdx.x) >> 5;
    float wj0 = eW[64 + 2 * lane], wj1 = eW[65 + 2 * lane];
    if (node >= n_src) return;
    float2 x = *reinterpret_cast<const float2*>(xsrc + (size_t)node * F + 2 * lane);
    float p = x.x * wj0 + x.y * wj1;
#pragma unroll
    for (int o = 16; o; o >>= 1) p += __shfl_xor_sync(0xffffffffu, p, o);
    if (!lane) dotj[node] = p;
}

// ======================= shared MLP helpers =======================
// Shared layout (floats): [0:8192) w1 packed, [8192:12288) w2 packed,
// [12288:12352) b1, [12352:12416) b2, [12416: ...) cat buffers (float2).
// Packed weight float4 e = kk*32+l : {w[2kk][2l], w[2kk][2l+1], w[2kk+1][2l], w[2kk+1][2l+1]}

__device__ __forceinline__ void load_weights(float* sm, const float* __restrict__ w1,
                                             const float* __restrict__ b1,
                                             const float* __restrict__ w2,
                                             const float* __restrict__ b2, int tid) {
    float4* w1p = reinterpret_cast<float4*>(sm);
    float4* w2p = reinterpret_cast<float4*>(sm + 8192);
    for (int e = tid; e < 2048; e += 256) {
        int kk = e >> 5, l = e & 31;
        float2 a = *reinterpret_cast<const float2*>(w1 + (2 * kk) * 64 + 2 * l);
        float2 b = *reinterpret_cast<const float2*>(w1 + (2 * kk + 1) * 64 + 2 * l);
        w1p[e] = make_float4(a.x, a.y, b.x, b.y);
    }
    for (int e = tid; e < 1024; e += 256) {
        int kk = e >> 5, l = e & 31;
        float2 a = *reinterpret_cast<const float2*>(w2 + (2 * kk) * 64 + 2 * l);
        float2 b = *reinterpret_cast<const float2*>(w2 + (2 * kk + 1) * 64 + 2 * l);
        w2p[e] = make_float4(a.x, a.y, b.x, b.y);
    }
    if (tid < 64) { sm[12288 + tid] = b1[tid]; sm[12352 + tid] = b2[tid]; }
}

// cw must hold the 128-wide duplicated cat vectors per target; outputs o[t] = mish(mlp).
__device__ __forceinline__ void mlp_apply(const float* sm, float2* cw, int lane, float2 o[NT]) {
    const float4* w1p = reinterpret_cast<const float4*>(sm);
    const float4* w2p = reinterpret_cast<const float4*>(sm + 8192);
    float2 acc[NT];
    float2 bv1 = *reinterpret_cast<const float2*>(sm + 12288 + 2 * lane);
#pragma unroll
    for (int t = 0; t < NT; t++) acc[t] = bv1;
#pragma unroll 4
    for (int kk = 0; kk < 64; kk++) {
        float4 wv = w1p[kk * 32 + lane];
#pragma unroll
        for (int t = 0; t < NT; t++) {
            float4 cv = *reinterpret_cast<const float4*>(cw + t * 128 + 2 * kk);
            acc[t] = ffma2(make_float2(wv.x, wv.y), make_float2(cv.x, cv.y), acc[t]);
            acc[t] = ffma2(make_float2(wv.z, wv.w), make_float2(cv.z, cv.w), acc[t]);
        }
    }
    __syncwarp();
#pragma unroll
    for (int t = 0; t < NT; t++) {
        float h0 = mishf(acc[t].x), h1 = mishf(acc[t].y);
        cw[t * 128 + 2 * lane]     = make_float2(h0, h0);
        cw[t * 128 + 2 * lane + 1] = make_float2(h1, h1);
    }
    __syncwarp();
    float2 bv2 = *reinterpret_cast<const float2*>(sm + 12352 + 2 * lane);
#pragma unroll
    for (int t = 0; t < NT; t++) acc[t] = bv2;
#pragma unroll 4
    for (int kk = 0; kk < 32; kk++) {
        float4 wv = w2p[kk * 32 + lane];
#pragma unroll
        for (int t = 0; t < NT; t++) {
            float4 cv = *reinterpret_cast<const float4*>(cw + t * 128 + 2 * kk);
            acc[t] = ffma2(make_float2(wv.x, wv.y), make_float2(cv.x, cv.y), acc[t]);
            acc[t] = ffma2(make_float2(wv.z, wv.w), make_float2(cv.z, cv.w), acc[t]);
        }
    }
#pragma unroll
    for (int t = 0; t < NT; t++) o[t] = make_float2(mishf(acc[t].x), mishf(acc[t].y));
}

// ======================= fused segment-reduce + MLP =======================
__global__ void __launch_bounds__(256, 2) fused_pass(
    const float* __restrict__ xsrc, const float* __restrict__ xtgt, int n_tgt,
    const int* __restrict__ ssrc, const int* __restrict__ offs, const int* __restrict__ cnt,
    const float* __restrict__ dotj,
    const float* __restrict__ eW, const float* __restrict__ eB,
    const float* __restrict__ w1, const float* __restrict__ b1,
    const float* __restrict__ w2, const float* __restrict__ b2,
    float* __restrict__ out) {
    extern __shared__ float sm[];
    float2* cats = reinterpret_cast<float2*>(sm + 12416);

    int tid = threadIdx.x;
    load_weights(sm, w1, b1, w2, b2, tid);
    __syncthreads();

    int warp = tid >> 5, lane = tid & 31;
    float wi0 = eW[2 * lane], wi1 = eW[2 * lane + 1];
    float bia = eB[0];
    float2* cw = cats + warp * NT * 128;
    int stride = gridDim.x * 8 * NT;

    for (int base = (blockIdx.x * 8 + warp) * NT; base < n_tgt; base += stride) {
        int nv = n_tgt - base; if (nv > NT) nv = NT;

        int o[NT], c[NT];
        float2 xiv[NT];
        float dot_i[NT];
#pragma unroll
        for (int t = 0; t < NT; t++) {
            bool v = (t < nv);
            size_t node = (size_t)(base + t);
            o[t] = v ? offs[node] : 0;
            c[t] = v ? cnt[node]  : 0;
            xiv[t] = v ? *reinterpret_cast<const float2*>(xtgt + node * F + 2 * lane)
                       : make_float2(0.f, 0.f);
            float p = xiv[t].x * wi0 + xiv[t].y * wi1;
#pragma unroll
            for (int off = 16; off; off >>= 1) p += __shfl_xor_sync(0xffffffffu, p, off);
            dot_i[t] = p + bia;
        }

        int maxc = c[0];
#pragma unroll
        for (int t = 1; t < NT; t++) maxc = max(maxc, c[t]);

        float den0[NT], num0[NT], den1[NT], num1[NT];
#pragma unroll
        for (int t = 0; t < NT; t++) { den0[t] = 0.f; num0[t] = 0.f; den1[t] = 0.f; num1[t] = 0.f; }

        for (int k = 0; k < maxc; k++) {
            float  djv[NT];
            float2 xjv[NT];
#pragma unroll
            for (int t = 0; t < NT; t++) {
                if (k < c[t]) {
                    int s = ssrc[o[t] + k];
                    djv[t] = dotj[s];
                    xjv[t] = *reinterpret_cast<const float2*>(xsrc + (size_t)s * F + 2 * lane);
                }
            }
#pragma unroll
            for (int t = 0; t < NT; t++) {
                if (k < c[t]) {
                    float z = dot_i[t] + djv[t];
                    float w = __fdividef(1.f, 1.f + __expf(-z));
                    float m0 = w * xjv[t].x, m1 = w * xjv[t].y;
                    float e0 = __expf(m0),   e1 = __expf(m1);
                    den0[t] += e0; num0[t] += e0 * m0;
                    den1[t] += e1; num1[t] += e1 * m1;
                }
            }
        }

#pragma unroll
        for (int t = 0; t < NT; t++) {
            float a0 = __fdividef(num0[t], den0[t] + 1e-16f);
            float a1 = __fdividef(num1[t], den1[t] + 1e-16f);
            cw[t * 128 + 2 * lane]          = make_float2(a0, a0);
            cw[t * 128 + 2 * lane + 1]      = make_float2(a1, a1);
            cw[t * 128 + 64 + 2 * lane]     = make_float2(xiv[t].x, xiv[t].x);
            cw[t * 128 + 64 + 2 * lane + 1] = make_float2(xiv[t].y, xiv[t].y);
        }
        __syncwarp();

        float2 ov[NT];
        mlp_apply(sm, cw, lane, ov);

#pragma unroll
        for (int t = 0; t < NT; t++) {
            if (t < nv) {
                *reinterpret_cast<float2*>(out + (size_t)(base + t) * F + 2 * lane) = ov[t];
            }
        }
        __syncwarp();
    }
}

// ======================= small-pass atomic path =======================

__global__ void edge_pass(const float* __restrict__ xsrc, const float* __restrict__ xtgt,
                          const int* __restrict__ src, const int* __restrict__ dst, int E,
                          const float* __restrict__ eW, const float* __restrict__ eB) {
    __shared__ float Ws[2 * F];
    __shared__ float Bs;
    int tid = threadIdx.x;
    if (tid < 2 * F) Ws[tid] = eW[tid];
    if (tid == 0) Bs = eB[0];
    __syncthreads();

    int lane = tid & 31;
    int e = blockIdx.x * (blockDim.x >> 5) + (tid >> 5);
    if (e >= E) return;

    int s = src[e], d = dst[e];
    float2 xj = *reinterpret_cast<const float2*>(xsrc + (size_t)s * F + 2 * lane);
    float2 xi = *reinterpret_cast<const float2*>(xtgt + (size_t)d * F + 2 * lane);

    float part = xi.x * Ws[2 * lane] + xi.y * Ws[2 * lane + 1]
               + xj.x * Ws[F + 2 * lane] + xj.y * Ws[F + 2 * lane + 1];
#pragma unroll
    for (int o = 16; o; o >>= 1) part += __shfl_xor_sync(0xffffffffu, part, o);

    float w = __fdividef(1.f, 1.f + __expf(-(part + Bs)));
    float m0 = w * xj.x, m1 = w * xj.y;
    float e0 = __expf(m0), e1 = __expf(m1);

    float4 v = make_float4(e0, e0 * m0, e1, e1 * m1);
    atomicAdd(reinterpret_cast<float4*>(g_acc + (size_t)d * 128 + 4 * lane), v);
}

__global__ void __launch_bounds__(256, 2) node_pass(
    const float* __restrict__ xtgt, int n_tgt,
    const float* __restrict__ w1, const float* __restrict__ b1,
    const float* __restrict__ w2, const float* __restrict__ b2,
    float* __restrict__ out, int accumulate) {
    extern __shared__ float sm[];
    float2* cats = reinterpret_cast<float2*>(sm + 12416);

    int tid = threadIdx.x;
    load_weights(sm, w1, b1, w2, b2, tid);
    __syncthreads();

    int warp = tid >> 5, lane = tid & 31;
    float2* cw = cats + warp * NT * 128;
    int stride = gridDim.x * 8 * NT;

    for (int base = (blockIdx.x * 8 + warp) * NT; base < n_tgt; base += stride) {
        int nv = n_tgt - base; if (nv > NT) nv = NT;

#pragma unroll
        for (int t = 0; t < NT; t++) {
            if (t < nv) {
                size_t node = (size_t)(base + t);
                float4* ap = reinterpret_cast<float4*>(g_acc + node * 128 + 4 * lane);
                float4 a = *ap;
                *ap = make_float4(0.f, 0.f, 0.f, 0.f);  // self-clean for replay
                float2 xt = *reinterpret_cast<const float2*>(xtgt + node * F + 2 * lane);
                float a0 = __fdividef(a.y, a.x + 1e-16f);
                float a1 = __fdividef(a.w, a.z + 1e-16f);
                cw[t * 128 + 2 * lane]          = make_float2(a0, a0);
                cw[t * 128 + 2 * lane + 1]      = make_float2(a1, a1);
                cw[t * 128 + 64 + 2 * lane]     = make_float2(xt.x, xt.x);
                cw[t * 128 + 64 + 2 * lane + 1] = make_float2(xt.y, xt.y);
            }
        }
        __syncwarp();

        float2 ov[NT];
        mlp_apply(sm, cw, lane, ov);

#pragma unroll
        for (int t = 0; t < NT; t++) {
            if (t < nv) {
                float2* op = reinterpret_cast<float2*>(out + (size_t)(base + t) * F + 2 * lane);
                float2 o = ov[t];
                if (accumulate) { float2 pv = *op; o.x += pv.x; o.y += pv.y; }
                *op = o;
            }
        }
        __syncwarp();
    }
}

// ======================= launcher =======================

extern "C" void kernel_launch(void* const* d_in, const int* in_sizes, int n_in,
                              void* d_out, int out_size) {
    const float* x_hit = (const float*)d_in[0];
    const float* x_sp  = (const float*)d_in[1];
    const float* x_oph = (const float*)d_in[2];
    const float* x_pmt = (const float*)d_in[3];
    const float* x_opf = (const float*)d_in[4];
    const float* x_evt = (const float*)d_in[5];
    const float* ew = (const float*)d_in[6];
    const float* eb = (const float*)d_in[7];
    const float* w1 = (const float*)d_in[8];
    const float* b1 = (const float*)d_in[9];
    const float* w2 = (const float*)d_in[10];
    const float* b2 = (const float*)d_in[11];
    const int* e_hit_sp  = (const int*)d_in[12];
    const int* e_oph_pmt = (const int*)d_in[13];
    const int* e_pmt_opf = (const int*)d_in[14];
    const int* e_sp_evt  = (const int*)d_in[15];
    const int* e_opf_evt = (const int*)d_in[16];
    const int* e_evt_sp  = (const int*)d_in[17];
    const int* e_sp_hit  = (const int*)d_in[18];
    const int* e_evt_opf = (const int*)d_in[19];
    const int* e_opf_pmt = (const int*)d_in[20];
    const int* e_pmt_oph = (const int*)d_in[21];

    float* out = (float*)d_out;
    float* d_p   = out;
    float* d_n   = d_p   + (size_t)N_HIT * F;
    float* d_oph = d_n   + (size_t)N_SP  * F;
    float* d_pmt = d_oph + (size_t)N_OPH * F;
    float* d_opf = d_pmt + (size_t)N_PMT * F;
    float* d_i   = d_opf + (size_t)N_OPF * F;

    float *pn, *ppmt, *popf, *pdotj;
    int *pcnt, *poffs, *pcur, *pssrc, *pbs;
    cudaGetSymbolAddress((void**)&pn,    g_nbuf);
    cudaGetSymbolAddress((void**)&ppmt,  g_pmtbuf);
    cudaGetSymbolAddress((void**)&popf,  g_opfbuf);
    cudaGetSymbolAddress((void**)&pdotj, g_dotj);
    cudaGetSymbolAddress((void**)&pcnt,  g_count);
    cudaGetSymbolAddress((void**)&poffs, g_offs);
    cudaGetSymbolAddress((void**)&pcur,  g_cursor);
    cudaGetSymbolAddress((void**)&pssrc, g_ssrc);
    cudaGetSymbolAddress((void**)&pbs,   g_bsums);

    const int SMEM = 82432;
    cudaFuncSetAttribute(node_pass,  cudaFuncAttributeMaxDynamicSharedMemorySize, SMEM);
    cudaFuncSetAttribute(fused_pass, cudaFuncAttributeMaxDynamicSharedMemorySize, SMEM);

    // Edge counts
    int E0 = in_sizes[12] / 2;  // hit->sp
    int E1 = in_sizes[13] / 2;  // oph->pmt
    int E2 = in_sizes[14] / 2;  // pmt->opf   (small)
    int E3 = in_sizes[15] / 2;  // sp->evt    (small)
    int E4 = in_sizes[16] / 2;  // opf->evt   (small)
    int E5 = in_sizes[17] / 2;  // evt->sp
    int E6 = in_sizes[18] / 2;  // sp->hit
    int E7 = in_sizes[19] / 2;  // evt->opf   (small)
    int E8 = in_sizes[20] / 2;  // opf->pmt
    int E9 = in_sizes[21] / 2;  // pmt->oph

    // ---- batched sort config for the 6 large passes (order: p0,p1,p5,p6,p8,p9) ----
    SortCfg cfg;
    const int* es[6] = { e_hit_sp, e_oph_pmt, e_evt_sp, e_sp_hit, e_opf_pmt, e_pmt_oph };
    int       ec[6] = { E0, E1, E5, E6, E8, E9 };
    int       tc[6] = { N_SP, N_PMT, N_SP, N_HIT, N_PMT, N_OPH };
    int ebase = 0, cbase = 0;
    for (int p = 0; p < 6; p++) {
        cfg.src[p]   = es[p];
        cfg.dst[p]   = es[p] + ec[p];
        cfg.ebase[p] = ebase;
        cfg.cbase[p] = cbase;
        ebase += ec[p];
        cbase += tc[p];
    }
    cfg.ebase[6] = ebase;
    int Etot = ebase;          // 1,510,000
    int Ctot = cbase;          // 660,000
    int nb = (Ctot + SCHUNK - 1) / SCHUNK;  // 81

    // dotj bases: p0(hit 300k), p1(oph 200k), p5(evt 256), p6(sp 50k), p8(opf 2k), p9(pmt 30k)
    const int db0 = 0, db1 = 300000, db5 = 500000, db6 = 501000, db8 = 551000, db9 = 553000;

    // ---- upfront preprocessing (6 launches + 2 dotj) ----
    zero_k     <<<296, 256>>>(pcnt, Ctot);
    hist_all   <<<(Etot + 255) / 256, 256>>>(cfg, Etot, pcnt);
    scan1_k    <<<nb, 256>>>(pcnt, Ctot, pbs);
    scan2_k    <<<1, 128>>>(pbs, nb);
    scan3_k    <<<nb, 256>>>(pcnt, pbs, Ctot, poffs, pcur);
    scatter_all<<<(Etot + 255) / 256, 256>>>(cfg, Etot, pcur, pssrc);
    dotj_k     <<<(N_HIT + 7) / 8, 256>>>(x_hit, N_HIT, ew + 0 * 128, pdotj + db0);
    dotj_k     <<<(N_OPH + 7) / 8, 256>>>(x_oph, N_OPH, ew + 1 * 128, pdotj + db1);

    auto fused = [&](int i, const float* xs, const float* xt, int n_tgt,
                     int cb, int db, float* o) {
        int fg = (n_tgt + 8 * NT - 1) / (8 * NT); if (fg > 296) fg = 296;
        fused_pass<<<fg, 256, SMEM>>>(xs, xt, n_tgt, pssrc, poffs + cb, pcnt + cb,
                                      pdotj + db, ew + (size_t)i * 128, eb + i,
                                      w1 + (size_t)i * 8192, b1 + (size_t)i * 64,
                                      w2 + (size_t)i * 4096, b2 + (size_t)i * 64, o);
    };

    auto small = [&](int i, const float* xs, const float* xt, const int* e, int E,
                     int n_tgt, float* o, int accf) {
        int grid = (E + 15) / 16;
        edge_pass<<<grid, 512>>>(xs, xt, e, e + E, E, ew + (size_t)i * 128, eb + i);
        int ng = (n_tgt + 8 * NT - 1) / (8 * NT); if (ng > 296) ng = 296;
        node_pass<<<ng, 256, SMEM>>>(xt, n_tgt, w1 + (size_t)i * 8192, b1 + (size_t)i * 64,
                                     w2 + (size_t)i * 4096, b2 + (size_t)i * 64, o, accf);
    };

    // ---- pass sequence ----
    fused(0, x_hit, x_sp,  N_SP,  cfg.cbase[0], db0, pn);           // plane_to_nexus
    fused(1, x_oph, x_pmt, N_PMT, cfg.cbase[1], db1, ppmt);         // hit_to_pmt
    small(2, ppmt,  x_opf, e_pmt_opf, E2, N_OPF, popf, 0);          // pmt_to_flash
    small(3, pn,    x_evt, e_sp_evt,  E3, N_EVT, d_i,  0);          // nexus_to_interaction
    small(4, popf,  x_evt, e_opf_evt, E4, N_EVT, d_i,  1);          // flash_to_interaction (sum)
    dotj_k<<<(N_EVT + 7) / 8, 256>>>(d_i, N_EVT, ew + 5 * 128, pdotj + db5);
    fused(5, d_i,   pn,    N_SP,  cfg.cbase[2], db5, d_n);          // interaction_to_nexus
    dotj_k<<<(N_SP + 7) / 8, 256>>>(d_n, N_SP, ew + 6 * 128, pdotj + db6);
    fused(6, d_n,   x_hit, N_HIT, cfg.cbase[3], db6, d_p);          // nexus_to_plane
    small(7, d_i,   popf,  e_evt_opf, E7, N_OPF, d_opf, 0);         // interaction_to_flash
    dotj_k<<<(N_OPF + 7) / 8, 256>>>(d_opf, N_OPF, ew + 8 * 128, pdotj + db8);
    fused(8, d_opf, ppmt,  N_PMT, cfg.cbase[4], db8, d_pmt);        // flash_to_pmt
    dotj_k<<<(N_PMT + 7) / 8, 256>>>(d_pmt, N_PMT, ew + 9 * 128, pdotj + db9);
    fused(9, d_pmt, x_oph, N_OPH, cfg.cbase[5], db9, d_oph);        // pmt_to_ophit
}

// round 6
// speedup vs baseline: 1.7064x; 1.1107x over previous
#include <cuda_runtime.h>

#define F 64
#define NT 4

// Node counts (fixed by the problem)
#define N_HIT 300000
#define N_SP   50000
#define N_OPH 200000
#define N_PMT  30000
#define N_OPF   2000
#define N_EVT    256

// Combined-sort totals (6 large passes: p0,p1,p5,p6,p8,p9)
#define CTOT 660000
#define ETOT 1510000
#define DTOT 600000

// ---- scratch (device globals) ----
// g_acc: [0 : 2000*128) opf-target passes (p2, p7) ; [2000*128 : 2256*128) evt-target passes (p3, p4)
__device__ float g_acc[(size_t)(N_OPF + N_EVT) * 128];
__device__ float g_nbuf[(size_t)N_SP * F];
__device__ float g_pmtbuf[(size_t)N_PMT * F];
__device__ float g_opfbuf[(size_t)N_OPF * F];
__device__ int   g_count[CTOT];
__device__ int   g_offs[CTOT];
__device__ int   g_cursor[CTOT];
__device__ int   g_ssrc[ETOT];
__device__ int   g_bsums[128];
__device__ float g_dotj[DTOT];

// Packed fp32x2 FMA (Blackwell FFMA2, only via PTX)
__device__ __forceinline__ float2 ffma2(float2 a, float2 b, float2 c) {
    unsigned long long ua = *reinterpret_cast<unsigned long long*>(&a);
    unsigned long long ub = *reinterpret_cast<unsigned long long*>(&b);
    unsigned long long uc = *reinterpret_cast<unsigned long long*>(&c);
    unsigned long long ud;
    asm("fma.rn.f32x2 %0, %1, %2, %3;" : "=l"(ud) : "l"(ua), "l"(ub), "l"(uc));
    return *reinterpret_cast<float2*>(&ud);
}

__device__ __forceinline__ float mishf(float x) {
    float e = __expf(fminf(x, 30.f));
    float t = e * (e + 2.f);
    return x * __fdividef(t, t + 2.f);
}

// ======================= batched sort machinery =======================

struct SortCfg {
    const int* src[6];
    const int* dst[6];
    int ebase[7];
    int cbase[6];
};

__global__ void zero_k(int* __restrict__ p, int n) {
    int i = blockIdx.x * blockDim.x + threadIdx.x;
    for (; i < n; i += gridDim.x * blockDim.x) p[i] = 0;
}

__global__ void hist_all(SortCfg cfg, int Etot, int* __restrict__ cnt) {
    int i = blockIdx.x * blockDim.x + threadIdx.x;
    if (i >= Etot) return;
    int s = 0;
    while (i >= cfg.ebase[s + 1]) s++;
    int li = i - cfg.ebase[s];
    atomicAdd(&cnt[cfg.cbase[s] + cfg.dst[s][li]], 1);
}

#define SCHUNK 8192
__global__ void scan1_k(const int* __restrict__ cnt, int n, int* __restrict__ bsums) {
    __shared__ int ts[256];
    int tid = threadIdx.x;
    int base = blockIdx.x * SCHUNK;
    int s = 0;
#pragma unroll
    for (int j = 0; j < 32; j++) {
        int i = base + j * 256 + tid;
        if (i < n) s += cnt[i];
    }
    ts[tid] = s; __syncthreads();
    for (int o = 128; o; o >>= 1) { if (tid < o) ts[tid] += ts[tid + o]; __syncthreads(); }
    if (!tid) bsums[blockIdx.x] = ts[0];
}

__global__ void scan2_k(int* __restrict__ bsums, int nb) {
    __shared__ int sb[128];
    int tid = threadIdx.x;
    if (tid < nb) sb[tid] = bsums[tid];
    __syncthreads();
    if (tid == 0) {
        int run = 0;
        for (int b = 0; b < nb; b++) { int t = sb[b]; sb[b] = run; run += t; }
    }
    __syncthreads();
    if (tid < nb) bsums[tid] = sb[tid];
}

__global__ void scan3_k(const int* __restrict__ cnt, const int* __restrict__ bsums, int n,
                        int* __restrict__ offs, int* __restrict__ cur) {
    __shared__ int ts[256];
    int tid = threadIdx.x;
    int base = blockIdx.x * SCHUNK + tid * 32;
    int v[32]; int s = 0;
#pragma unroll
    for (int j = 0; j < 32; j++) {
        int i = base + j;
        v[j] = (i < n) ? cnt[i] : 0;
        s += v[j];
    }
    ts[tid] = s; __syncthreads();
    for (int off = 1; off < 256; off <<= 1) {
        int add = (tid >= off) ? ts[tid - off] : 0;
        __syncthreads();
        ts[tid] += add;
        __syncthreads();
    }
    int run = (tid ? ts[tid - 1] : 0) + bsums[blockIdx.x];
#pragma unroll
    for (int j = 0; j < 32; j++) {
        int i = base + j;
        if (i < n) { offs[i] = run; cur[i] = run; run += v[j]; }
    }
}

__global__ void scatter_all(SortCfg cfg, int Etot, int* __restrict__ cur, int* __restrict__ ssrc) {
    int i = blockIdx.x * blockDim.x + threadIdx.x;
    if (i >= Etot) return;
    int s = 0;
    while (i >= cfg.ebase[s + 1]) s++;
    int li = i - cfg.ebase[s];
    int pos = atomicAdd(&cur[cfg.cbase[s] + cfg.dst[s][li]], 1);
    ssrc[pos] = cfg.src[s][li];
}

__global__ void dotj_k(const float* __restrict__ xsrc, int n_src,
                       const float* __restrict__ eW, float* __restrict__ dotj) {
    int lane = threadIdx.x & 31;
    int node = (blockIdx.x * blockDim.x + threadIdx.x) >> 5;
    float wj0 = eW[64 + 2 * lane], wj1 = eW[65 + 2 * lane];
    if (node >= n_src) return;
    float2 x = *reinterpret_cast<const float2*>(xsrc + (size_t)node * F + 2 * lane);
    float p = x.x * wj0 + x.y * wj1;
#pragma unroll
    for (int o = 16; o; o >>= 1) p += __shfl_xor_sync(0xffffffffu, p, o);
    if (!lane) dotj[node] = p;
}

// ======================= shared MLP helpers =======================

__device__ __forceinline__ void load_weights(float* sm, const float* __restrict__ w1,
                                             const float* __restrict__ b1,
                                             const float* __restrict__ w2,
                                             const float* __restrict__ b2, int tid) {
    float4* w1p = reinterpret_cast<float4*>(sm);
    float4* w2p = reinterpret_cast<float4*>(sm + 8192);
    for (int e = tid; e < 2048; e += 256) {
        int kk = e >> 5, l = e & 31;
        float2 a = *reinterpret_cast<const float2*>(w1 + (2 * kk) * 64 + 2 * l);
        float2 b = *reinterpret_cast<const float2*>(w1 + (2 * kk + 1) * 64 + 2 * l);
        w1p[e] = make_float4(a.x, a.y, b.x, b.y);
    }
    for (int e = tid; e < 1024; e += 256) {
        int kk = e >> 5, l = e & 31;
        float2 a = *reinterpret_cast<const float2*>(w2 + (2 * kk) * 64 + 2 * l);
        float2 b = *reinterpret_cast<const float2*>(w2 + (2 * kk + 1) * 64 + 2 * l);
        w2p[e] = make_float4(a.x, a.y, b.x, b.y);
    }
    if (tid < 64) { sm[12288 + tid] = b1[tid]; sm[12352 + tid] = b2[tid]; }
}

__device__ __forceinline__ void mlp_apply(const float* sm, float2* cw, int lane, float2 o[NT]) {
    const float4* w1p = reinterpret_cast<const float4*>(sm);
    const float4* w2p = reinterpret_cast<const float4*>(sm + 8192);
    float2 acc[NT];
    float2 bv1 = *reinterpret_cast<const float2*>(sm + 12288 + 2 * lane);
#pragma unroll
    for (int t = 0; t < NT; t++) acc[t] = bv1;
#pragma unroll 4
    for (int kk = 0; kk < 64; kk++) {
        float4 wv = w1p[kk * 32 + lane];
#pragma unroll
        for (int t = 0; t < NT; t++) {
            float4 cv = *reinterpret_cast<const float4*>(cw + t * 128 + 2 * kk);
            acc[t] = ffma2(make_float2(wv.x, wv.y), make_float2(cv.x, cv.y), acc[t]);
            acc[t] = ffma2(make_float2(wv.z, wv.w), make_float2(cv.z, cv.w), acc[t]);
        }
    }
    __syncwarp();
#pragma unroll
    for (int t = 0; t < NT; t++) {
        float h0 = mishf(acc[t].x), h1 = mishf(acc[t].y);
        cw[t * 128 + 2 * lane]     = make_float2(h0, h0);
        cw[t * 128 + 2 * lane + 1] = make_float2(h1, h1);
    }
    __syncwarp();
    float2 bv2 = *reinterpret_cast<const float2*>(sm + 12352 + 2 * lane);
#pragma unroll
    for (int t = 0; t < NT; t++) acc[t] = bv2;
#pragma unroll 4
    for (int kk = 0; kk < 32; kk++) {
        float4 wv = w2p[kk * 32 + lane];
#pragma unroll
        for (int t = 0; t < NT; t++) {
            float4 cv = *reinterpret_cast<const float4*>(cw + t * 128 + 2 * kk);
            acc[t] = ffma2(make_float2(wv.x, wv.y), make_float2(cv.x, cv.y), acc[t]);
            acc[t] = ffma2(make_float2(wv.z, wv.w), make_float2(cv.z, cv.w), acc[t]);
        }
    }
#pragma unroll
    for (int t = 0; t < NT; t++) o[t] = make_float2(mishf(acc[t].x), mishf(acc[t].y));
}

// ======================= fused segment-reduce + MLP =======================
__global__ void __launch_bounds__(256, 2) fused_pass(
    const float* __restrict__ xsrc, const float* __restrict__ xtgt, int n_tgt,
    const int* __restrict__ ssrc, const int* __restrict__ offs, const int* __restrict__ cnt,
    const float* __restrict__ dotj,
    const float* __restrict__ eW, const float* __restrict__ eB,
    const float* __restrict__ w1, const float* __restrict__ b1,
    const float* __restrict__ w2, const float* __restrict__ b2,
    float* __restrict__ out) {
    extern __shared__ float sm[];
    float2* cats = reinterpret_cast<float2*>(sm + 12416);

    int tid = threadIdx.x;
    load_weights(sm, w1, b1, w2, b2, tid);
    __syncthreads();

    int warp = tid >> 5, lane = tid & 31;
    float wi0 = eW[2 * lane], wi1 = eW[2 * lane + 1];
    float bia = eB[0];
    float2* cw = cats + warp * NT * 128;
    int stride = gridDim.x * 8 * NT;

    for (int base = (blockIdx.x * 8 + warp) * NT; base < n_tgt; base += stride) {
        int nv = n_tgt - base; if (nv > NT) nv = NT;

        int o[NT], c[NT];
        float2 xiv[NT];
        float dot_i[NT];
#pragma unroll
        for (int t = 0; t < NT; t++) {
            bool v = (t < nv);
            size_t node = (size_t)(base + t);
            o[t] = v ? offs[node] : 0;
            c[t] = v ? cnt[node]  : 0;
            xiv[t] = v ? *reinterpret_cast<const float2*>(xtgt + node * F + 2 * lane)
                       : make_float2(0.f, 0.f);
            float p = xiv[t].x * wi0 + xiv[t].y * wi1;
#pragma unroll
            for (int off = 16; off; off >>= 1) p += __shfl_xor_sync(0xffffffffu, p, off);
            dot_i[t] = p + bia;
        }

        int maxc = c[0];
#pragma unroll
        for (int t = 1; t < NT; t++) maxc = max(maxc, c[t]);

        float den0[NT], num0[NT], den1[NT], num1[NT];
#pragma unroll
        for (int t = 0; t < NT; t++) { den0[t] = 0.f; num0[t] = 0.f; den1[t] = 0.f; num1[t] = 0.f; }

        for (int k = 0; k < maxc; k++) {
            float  djv[NT];
            float2 xjv[NT];
#pragma unroll
            for (int t = 0; t < NT; t++) {
                if (k < c[t]) {
                    int s = ssrc[o[t] + k];
                    djv[t] = dotj[s];
                    xjv[t] = *reinterpret_cast<const float2*>(xsrc + (size_t)s * F + 2 * lane);
                }
            }
#pragma unroll
            for (int t = 0; t < NT; t++) {
                if (k < c[t]) {
                    float z = dot_i[t] + djv[t];
                    float w = __fdividef(1.f, 1.f + __expf(-z));
                    float m0 = w * xjv[t].x, m1 = w * xjv[t].y;
                    float e0 = __expf(m0),   e1 = __expf(m1);
                    den0[t] += e0; num0[t] += e0 * m0;
                    den1[t] += e1; num1[t] += e1 * m1;
                }
            }
        }

#pragma unroll
        for (int t = 0; t < NT; t++) {
            float a0 = __fdividef(num0[t], den0[t] + 1e-16f);
            float a1 = __fdividef(num1[t], den1[t] + 1e-16f);
            cw[t * 128 + 2 * lane]          = make_float2(a0, a0);
            cw[t * 128 + 2 * lane + 1]      = make_float2(a1, a1);
            cw[t * 128 + 64 + 2 * lane]     = make_float2(xiv[t].x, xiv[t].x);
            cw[t * 128 + 64 + 2 * lane + 1] = make_float2(xiv[t].y, xiv[t].y);
        }
        __syncwarp();

        float2 ov[NT];
        mlp_apply(sm, cw, lane, ov);

#pragma unroll
        for (int t = 0; t < NT; t++) {
            if (t < nv) {
                *reinterpret_cast<float2*>(out + (size_t)(base + t) * F + 2 * lane) = ov[t];
            }
        }
        __syncwarp();
    }
}

// ======================= small-pass atomic path =======================

__global__ void edge_pass(const float* __restrict__ xsrc, const float* __restrict__ xtgt,
                          const int* __restrict__ src, const int* __restrict__ dst, int E,
                          const float* __restrict__ eW, const float* __restrict__ eB,
                          float* __restrict__ acc) {
    __shared__ float Ws[2 * F];
    __shared__ float Bs;
    int tid = threadIdx.x;
    if (tid < 2 * F) Ws[tid] = eW[tid];
    if (tid == 0) Bs = eB[0];
    __syncthreads();

    int lane = tid & 31;
    int e = blockIdx.x * (blockDim.x >> 5) + (tid >> 5);
    if (e >= E) return;

    int s = src[e], d = dst[e];
    float2 xj = *reinterpret_cast<const float2*>(xsrc + (size_t)s * F + 2 * lane);
    float2 xi = *reinterpret_cast<const float2*>(xtgt + (size_t)d * F + 2 * lane);

    float part = xi.x * Ws[2 * lane] + xi.y * Ws[2 * lane + 1]
               + xj.x * Ws[F + 2 * lane] + xj.y * Ws[F + 2 * lane + 1];
#pragma unroll
    for (int o = 16; o; o >>= 1) part += __shfl_xor_sync(0xffffffffu, part, o);

    float w = __fdividef(1.f, 1.f + __expf(-(part + Bs)));
    float m0 = w * xj.x, m1 = w * xj.y;
    float e0 = __expf(m0), e1 = __expf(m1);

    float4 v = make_float4(e0, e0 * m0, e1, e1 * m1);
    atomicAdd(reinterpret_cast<float4*>(acc + (size_t)d * 128 + 4 * lane), v);
}

__global__ void __launch_bounds__(256, 2) node_pass(
    const float* __restrict__ xtgt, int n_tgt,
    const float* __restrict__ w1, const float* __restrict__ b1,
    const float* __restrict__ w2, const float* __restrict__ b2,
    float* __restrict__ out, int accumulate, float* __restrict__ accbuf) {
    extern __shared__ float sm[];
    float2* cats = reinterpret_cast<float2*>(sm + 12416);

    int tid = threadIdx.x;
    load_weights(sm, w1, b1, w2, b2, tid);
    __syncthreads();

    int warp = tid >> 5, lane = tid & 31;
    float2* cw = cats + warp * NT * 128;
    int stride = gridDim.x * 8 * NT;

    for (int base = (blockIdx.x * 8 + warp) * NT; base < n_tgt; base += stride) {
        int nv = n_tgt - base; if (nv > NT) nv = NT;

#pragma unroll
        for (int t = 0; t < NT; t++) {
            if (t < nv) {
                size_t node = (size_t)(base + t);
                float4* ap = reinterpret_cast<float4*>(accbuf + node * 128 + 4 * lane);
                float4 a = *ap;
                *ap = make_float4(0.f, 0.f, 0.f, 0.f);  // self-clean for replay
                float2 xt = *reinterpret_cast<const float2*>(xtgt + node * F + 2 * lane);
                float a0 = __fdividef(a.y, a.x + 1e-16f);
                float a1 = __fdividef(a.w, a.z + 1e-16f);
                cw[t * 128 + 2 * lane]          = make_float2(a0, a0);
                cw[t * 128 + 2 * lane + 1]      = make_float2(a1, a1);
                cw[t * 128 + 64 + 2 * lane]     = make_float2(xt.x, xt.x);
                cw[t * 128 + 64 + 2 * lane + 1] = make_float2(xt.y, xt.y);
            }
        }
        __syncwarp();

        float2 ov[NT];
        mlp_apply(sm, cw, lane, ov);

#pragma unroll
        for (int t = 0; t < NT; t++) {
            if (t < nv) {
                float2* op = reinterpret_cast<float2*>(out + (size_t)(base + t) * F + 2 * lane);
                float2 o = ov[t];
                if (accumulate) { float2 pv = *op; o.x += pv.x; o.y += pv.y; }
                *op = o;
            }
        }
        __syncwarp();
    }
}

// ======================= launcher =======================

extern "C" void kernel_launch(void* const* d_in, const int* in_sizes, int n_in,
                              void* d_out, int out_size) {
    const float* x_hit = (const float*)d_in[0];
    const float* x_sp  = (const float*)d_in[1];
    const float* x_oph = (const float*)d_in[2];
    const float* x_pmt = (const float*)d_in[3];
    const float* x_opf = (const float*)d_in[4];
    const float* x_evt = (const float*)d_in[5];
    const float* ew = (const float*)d_in[6];
    const float* eb = (const float*)d_in[7];
    const float* w1 = (const float*)d_in[8];
    const float* b1 = (const float*)d_in[9];
    const float* w2 = (const float*)d_in[10];
    const float* b2 = (const float*)d_in[11];
    const int* e_hit_sp  = (const int*)d_in[12];
    const int* e_oph_pmt = (const int*)d_in[13];
    const int* e_pmt_opf = (const int*)d_in[14];
    const int* e_sp_evt  = (const int*)d_in[15];
    const int* e_opf_evt = (const int*)d_in[16];
    const int* e_evt_sp  = (const int*)d_in[17];
    const int* e_sp_hit  = (const int*)d_in[18];
    const int* e_evt_opf = (const int*)d_in[19];
    const int* e_opf_pmt = (const int*)d_in[20];
    const int* e_pmt_oph = (const int*)d_in[21];

    float* out = (float*)d_out;
    float* d_p   = out;
    float* d_n   = d_p   + (size_t)N_HIT * F;
    float* d_oph = d_n   + (size_t)N_SP  * F;
    float* d_pmt = d_oph + (size_t)N_OPH * F;
    float* d_opf = d_pmt + (size_t)N_PMT * F;
    float* d_i   = d_opf + (size_t)N_OPF * F;

    float *pacc, *pn, *ppmt, *popf, *pdotj;
    int *pcnt, *poffs, *pcur, *pssrc, *pbs;
    cudaGetSymbolAddress((void**)&pacc,  g_acc);
    cudaGetSymbolAddress((void**)&pn,    g_nbuf);
    cudaGetSymbolAddress((void**)&ppmt,  g_pmtbuf);
    cudaGetSymbolAddress((void**)&popf,  g_opfbuf);
    cudaGetSymbolAddress((void**)&pdotj, g_dotj);
    cudaGetSymbolAddress((void**)&pcnt,  g_count);
    cudaGetSymbolAddress((void**)&poffs, g_offs);
    cudaGetSymbolAddress((void**)&pcur,  g_cursor);
    cudaGetSymbolAddress((void**)&pssrc, g_ssrc);
    cudaGetSymbolAddress((void**)&pbs,   g_bsums);

    float* acc_opf = pacc;                          // p2, p7
    float* acc_evt = pacc + (size_t)N_OPF * 128;    // p3, p4

    const int SMEM = 82432;
    cudaFuncSetAttribute(node_pass,  cudaFuncAttributeMaxDynamicSharedMemorySize, SMEM);
    cudaFuncSetAttribute(fused_pass, cudaFuncAttributeMaxDynamicSharedMemorySize, SMEM);

    // Persistent side stream + fork/join events (created on first, uncaptured call)
    static cudaStream_t s1 = nullptr;
    static cudaEvent_t evA = nullptr, evB = nullptr, evC = nullptr, evD = nullptr,
                       evE = nullptr, evF = nullptr;
    if (!s1) {
        cudaStreamCreateWithFlags(&s1, cudaStreamNonBlocking);
        cudaEventCreateWithFlags(&evA, cudaEventDisableTiming);
        cudaEventCreateWithFlags(&evB, cudaEventDisableTiming);
        cudaEventCreateWithFlags(&evC, cudaEventDisableTiming);
        cudaEventCreateWithFlags(&evD, cudaEventDisableTiming);
        cudaEventCreateWithFlags(&evE, cudaEventDisableTiming);
        cudaEventCreateWithFlags(&evF, cudaEventDisableTiming);
    }
    cudaStream_t s0 = 0;

    // Edge counts
    int E0 = in_sizes[12] / 2;
    int E1 = in_sizes[13] / 2;
    int E2 = in_sizes[14] / 2;
    int E3 = in_sizes[15] / 2;
    int E4 = in_sizes[16] / 2;
    int E5 = in_sizes[17] / 2;
    int E6 = in_sizes[18] / 2;
    int E7 = in_sizes[19] / 2;
    int E8 = in_sizes[20] / 2;
    int E9 = in_sizes[21] / 2;

    // ---- batched sort config (order: p0,p1,p5,p6,p8,p9) ----
    SortCfg cfg;
    const int* es[6] = { e_hit_sp, e_oph_pmt, e_evt_sp, e_sp_hit, e_opf_pmt, e_pmt_oph };
    int       ec[6] = { E0, E1, E5, E6, E8, E9 };
    int       tc[6] = { N_SP, N_PMT, N_SP, N_HIT, N_PMT, N_OPH };
    int ebase = 0, cbase = 0;
    for (int p = 0; p < 6; p++) {
        cfg.src[p]   = es[p];
        cfg.dst[p]   = es[p] + ec[p];
        cfg.ebase[p] = ebase;
        cfg.cbase[p] = cbase;
        ebase += ec[p];
        cbase += tc[p];
    }
    cfg.ebase[6] = ebase;
    int Etot = ebase;
    int Ctot = cbase;
    int nb = (Ctot + SCHUNK - 1) / SCHUNK;

    const int db0 = 0, db1 = 300000, db5 = 500000, db6 = 501000, db8 = 551000, db9 = 553000;

    auto fused = [&](int i, const float* xs, const float* xt, int n_tgt,
                     int cb, int db, float* o, cudaStream_t st) {
        int fg = (n_tgt + 8 * NT - 1) / (8 * NT); if (fg > 296) fg = 296;
        fused_pass<<<fg, 256, SMEM, st>>>(xs, xt, n_tgt, pssrc, poffs + cb, pcnt + cb,
                                          pdotj + db, ew + (size_t)i * 128, eb + i,
                                          w1 + (size_t)i * 8192, b1 + (size_t)i * 64,
                                          w2 + (size_t)i * 4096, b2 + (size_t)i * 64, o);
    };

    auto small = [&](int i, const float* xs, const float* xt, const int* e, int E,
                     int n_tgt, float* o, int accf, float* accbuf, cudaStream_t st) {
        int grid = (E + 15) / 16;
        edge_pass<<<grid, 512, 0, st>>>(xs, xt, e, e + E, E, ew + (size_t)i * 128, eb + i, accbuf);
        int ng = (n_tgt + 8 * NT - 1) / (8 * NT); if (ng > 296) ng = 296;
        node_pass<<<ng, 256, SMEM, st>>>(xt, n_tgt, w1 + (size_t)i * 8192, b1 + (size_t)i * 64,
                                         w2 + (size_t)i * 4096, b2 + (size_t)i * 64,
                                         o, accf, accbuf);
    };

    // ==== Phase 1: preprocessing (s0) ∥ dotj0+dotj1 (s1) ====
    cudaEventRecord(evA, s0);
    cudaStreamWaitEvent(s1, evA, 0);

    zero_k     <<<296, 256, 0, s0>>>(pcnt, Ctot);
    hist_all   <<<(Etot + 255) / 256, 256, 0, s0>>>(cfg, Etot, pcnt);
    scan1_k    <<<nb, 256, 0, s0>>>(pcnt, Ctot, pbs);
    scan2_k    <<<1, 128, 0, s0>>>(pbs, nb);
    scan3_k    <<<nb, 256, 0, s0>>>(pcnt, pbs, Ctot, poffs, pcur);
    scatter_all<<<(Etot + 255) / 256, 256, 0, s0>>>(cfg, Etot, pcur, pssrc);

    dotj_k<<<(N_HIT + 7) / 8, 256, 0, s1>>>(x_hit, N_HIT, ew + 0 * 128, pdotj + db0);
    dotj_k<<<(N_OPH + 7) / 8, 256, 0, s1>>>(x_oph, N_OPH, ew + 1 * 128, pdotj + db1);

    cudaEventRecord(evB, s1);
    cudaStreamWaitEvent(s0, evB, 0);

    // ==== Phase 2: {p0, p3} on s0  ∥  {p1, p2} on s1 ====
    cudaEventRecord(evC, s0);
    cudaStreamWaitEvent(s1, evC, 0);

    fused(0, x_hit, x_sp, N_SP, cfg.cbase[0], db0, pn, s0);                 // plane_to_nexus
    small(3, pn, x_evt, e_sp_evt, E3, N_EVT, d_i, 0, acc_evt, s0);          // nexus_to_interaction

    fused(1, x_oph, x_pmt, N_PMT, cfg.cbase[1], db1, ppmt, s1);             // hit_to_pmt
    small(2, ppmt, x_opf, e_pmt_opf, E2, N_OPF, popf, 0, acc_opf, s1);      // pmt_to_flash

    cudaEventRecord(evD, s1);
    cudaStreamWaitEvent(s0, evD, 0);

    // ==== Phase 3: p4 (needs popf + d_i) on s0 ====
    small(4, popf, x_evt, e_opf_evt, E4, N_EVT, d_i, 1, acc_evt, s0);       // flash_to_interaction

    // ==== Phase 4: {dotj5,p5,dotj6,p6} on s0 ∥ {p7,dotj8,p8,dotj9,p9} on s1 ====
    cudaEventRecord(evE, s0);
    cudaStreamWaitEvent(s1, evE, 0);

    dotj_k<<<(N_EVT + 7) / 8, 256, 0, s0>>>(d_i, N_EVT, ew + 5 * 128, pdotj + db5);
    fused(5, d_i, pn, N_SP, cfg.cbase[2], db5, d_n, s0);                    // interaction_to_nexus
    dotj_k<<<(N_SP + 7) / 8, 256, 0, s0>>>(d_n, N_SP, ew + 6 * 128, pdotj + db6);
    fused(6, d_n, x_hit, N_HIT, cfg.cbase[3], db6, d_p, s0);                // nexus_to_plane

    small(7, d_i, popf, e_evt_opf, E7, N_OPF, d_opf, 0, acc_opf, s1);       // interaction_to_flash
    dotj_k<<<(N_OPF + 7) / 8, 256, 0, s1>>>(d_opf, N_OPF, ew + 8 * 128, pdotj + db8);
    fused(8, d_opf, ppmt, N_PMT, cfg.cbase[4], db8, d_pmt, s1);             // flash_to_pmt
    dotj_k<<<(N_PMT + 7) / 8, 256, 0, s1>>>(d_pmt, N_PMT, ew + 9 * 128, pdotj + db9);
    fused(9, d_pmt, x_oph, N_OPH, cfg.cbase[5], db9, d_oph, s1);            // pmt_to_ophit

    cudaEventRecord(evF, s1);
    cudaStreamWaitEvent(s0, evF, 0);
}